// round 15
// baseline (speedup 1.0000x reference)
#include <cuda_runtime.h>
#include <cuda_fp16.h>
#include <math.h>
#include <stdint.h>

#define NE 2048
#define SCALE 0.04419417382415922f   /* 1/sqrt(2*256) */

// ---------------- device scratch (static globals; no allocation) ----------------
__device__ __align__(16) __half g_x16[(size_t)NE * 64 * 512];   // x NHWC fp16
__device__ __align__(16) __half g_w1b[3][72 * 256 * 72];        // conv1 W chunk64-blocked pitch-144B
__device__ __align__(16) __half g_w2b[3][36 * 256 * 72];        // conv2 W chunk64-blocked
__device__ __align__(16) __half g_m1[3][(size_t)73728 * 256];   // conv1 out fp16
__device__ float g_qkv[3][(size_t)NE * 4096];                   // conv2 out fp32
__device__ int   g_stride;

// ---------------- PTX helpers (compute_103 base ISA only) -------------------------
__device__ __forceinline__ uint32_t smem_u32(const void* p) {
    uint32_t a;
    asm("{ .reg .u64 t; cvta.to.shared.u64 t, %1; cvt.u32.u64 %0, t; }" : "=r"(a) : "l"(p));
    return a;
}
__device__ __forceinline__ void cpa16(uint32_t dst, const void* src) {
    asm volatile("cp.async.cg.shared.global [%0], [%1], 16;" :: "r"(dst), "l"(src) : "memory");
}
#define CP_COMMIT() asm volatile("cp.async.commit_group;" ::: "memory")
#define CP_WAIT1()  asm volatile("cp.async.wait_group 1;" ::: "memory")
#define CP_WAIT0()  asm volatile("cp.async.wait_group 0;" ::: "memory")

__device__ __forceinline__ void bulk_g2s(uint32_t dst, const void* src, uint32_t bytes,
                                         uint32_t mbar) {
    asm volatile("cp.async.bulk.shared::cluster.global.mbarrier::complete_tx::bytes "
                 "[%0], [%1], %2, [%3];"
                 :: "r"(dst), "l"(src), "r"(bytes), "r"(mbar) : "memory");
}
#define MBINIT(mb, c)    asm volatile("mbarrier.init.shared.b64 [%0], %1;" :: "r"(mb), "r"(c) : "memory")
#define MBEXPECT(mb, tx) asm volatile("mbarrier.arrive.expect_tx.shared.b64 _, [%0], %1;" :: "r"(mb), "r"(tx) : "memory")

#define MBWAIT(mb, ph) do {                                                              \
    uint32_t _m = (mb); uint32_t _p = (ph); uint32_t _d;                                 \
    asm volatile("{\n\t.reg .pred p;\n\t"                                                \
        "mbarrier.try_wait.parity.acquire.cta.shared::cta.b64 p, [%1], %2;\n\t"          \
        "selp.b32 %0, 1, 0, p;\n\t}" : "=r"(_d) : "r"(_m), "r"(_p) : "memory");          \
    if (!_d) {                                                                           \
        asm volatile("{\n\t.reg .pred P1;\n\t"                                           \
            "WL_%=:\n\t"                                                                 \
            "mbarrier.try_wait.parity.acquire.cta.shared::cta.b64 P1, [%0], %1, 0x989680;\n\t" \
            "@P1 bra.uni WD_%=;\n\t"                                                     \
            "bra.uni WL_%=;\n\t"                                                         \
            "WD_%=:\n\t}" :: "r"(_m), "r"(_p) : "memory");                               \
    }                                                                                    \
} while (0)

__device__ __forceinline__ void ldm4(uint32_t* r, uint32_t addr) {
    asm volatile("ldmatrix.sync.aligned.m8n8.x4.shared.b16 {%0,%1,%2,%3}, [%4];"
        : "=r"(r[0]), "=r"(r[1]), "=r"(r[2]), "=r"(r[3]) : "r"(addr));
}
__device__ __forceinline__ void mma16816(float* d, const uint32_t* a, uint32_t b0, uint32_t b1) {
    asm volatile("mma.sync.aligned.m16n8k16.row.col.f32.f16.f16.f32 "
        "{%0,%1,%2,%3}, {%4,%5,%6,%7}, {%8,%9}, {%0,%1,%2,%3};"
        : "+f"(d[0]), "+f"(d[1]), "+f"(d[2]), "+f"(d[3])
        : "r"(a[0]), "r"(a[1]), "r"(a[2]), "r"(a[3]), "r"(b0), "r"(b1));
}

// ---------------- graph-id dtype detection ---------------------------------------
__global__ void k_detect(const int* __restrict__ gid32) {
    __shared__ int bad;
    if (threadIdx.x == 0) bad = 0;
    __syncthreads();
    for (int i = threadIdx.x; i < NE - 1; i += blockDim.x)
        if (gid32[i] > gid32[i + 1]) bad = 1;
    __syncthreads();
    if (threadIdx.x == 0) g_stride = bad ? 2 : 1;
}

// ---------------- prep: x NCHW fp32 -> NHWC fp16 ----------------------------------
__global__ void k_prep_x(const float* __restrict__ x) {      // grid (2048, 8), 256 thr
    __shared__ float tile[64][65];
    const int n = blockIdx.x, cc = blockIdx.y;
#pragma unroll
    for (int i = 0; i < 16; ++i) {
        int t = threadIdx.x + i * 256;
        int ci = t >> 6, yx = t & 63;
        tile[ci][yx] = x[(size_t)n * 32768 + (cc * 64 + ci) * 64 + yx];
    }
    __syncthreads();
#pragma unroll
    for (int i = 0; i < 16; ++i) {
        int t = threadIdx.x + i * 256;
        int yx = t >> 6, ci = t & 63;
        size_t o = ((size_t)n * 64 + yx) * 512 + cc * 64 + ci;
        g_x16[o] = __float2half_rn(tile[ci][yx]);
    }
}

// ---------------- prep: weights -> chunk64-blocked [c][cout][72] (pitch 144B) -----
__global__ void k_prep_w1(const float* __restrict__ wq, const float* __restrict__ wk,
                          const float* __restrict__ wv) {    // grid (72, 3), 256 thr
    const int c = blockIdx.x, h = blockIdx.y;
    const float* w = (h == 0) ? wq : (h == 1) ? wk : wv;
    const int kpos = c >> 3, coff = (c & 7) * 64;
    const int cout = threadIdx.x;
    __half* dst = g_w1b[h] + ((size_t)c * 256 + cout) * 72;
#pragma unroll
    for (int j = 0; j < 64; ++j)
        dst[j] = __float2half_rn(w[cout * 4608 + (coff + j) * 9 + kpos]);
#pragma unroll
    for (int j = 64; j < 72; ++j) dst[j] = __float2half_rn(0.f);
}

__global__ void k_prep_w2(const float* __restrict__ wq, const float* __restrict__ wk,
                          const float* __restrict__ wv) {    // grid (36, 3), 256 thr
    const int c = blockIdx.x, h = blockIdx.y;
    const float* w = (h == 0) ? wq : (h == 1) ? wk : wv;
    const int kpos = c >> 2, coff = (c & 3) * 64;
    const int cout = threadIdx.x;
    __half* dst = g_w2b[h] + ((size_t)c * 256 + cout) * 72;
#pragma unroll
    for (int j = 0; j < 64; ++j)
        dst[j] = __float2half_rn(w[cout * 2304 + (coff + j) * 9 + kpos]);
#pragma unroll
    for (int j = 64; j < 72; ++j) dst[j] = __float2half_rn(0.f);
}

// ---------------- HMMA GEMM: conv1 (PHASE 1) / conv2 (PHASE 2) --------------------
// CTA: M=64 x N=256, 128 threads (4 warps of 64x64), 2 CTAs/SM. K chunks of 64.
// A: 3 stages x 8KB (pitch 128, XOR swizzle), cp.async.cg, issued after top barrier.
// B: 2 stages x 36KB (pitch 144), ONE bulk each, issued after bottom barrier.
// Intra-chunk: frags double-buffered — load ks+1 while issuing MMAs of ks.
#define A_STAGE     8192
#define A_PITCH     128
#define B_BASE      24576
#define B_STAGE     36864
#define B_PITCH     144
#define B_BYTES     36864u
#define SMEM_DYN    98304
#define EPI_PITCH   260

template <int PHASE>
__global__ void __launch_bounds__(128, 2)
k_gemm(const float* __restrict__ bq, const float* __restrict__ bk,
       const float* __restrict__ bv) {
    extern __shared__ __align__(1024) char dsm[];
    const uint32_t sbase = smem_u32(dsm);

    const int tile = blockIdx.x, head = blockIdx.y;
    const int tid  = threadIdx.x, wid = tid >> 5, lane = tid & 31;
    const int wn   = wid * 64;               // warp n offset (wm = 0 for all)
    const float* bias = (head == 0) ? bq : (head == 1) ? bk : bv;

    __shared__ int s_basix[64];
    __shared__ __align__(8) unsigned long long s_mb[2];   // B full barriers

    constexpr int CHUNKS = (PHASE == 1) ? 72 : 36;
    constexpr int CPK    = (PHASE == 1) ? 8 : 4;

    if (tid < 64) {
        int m = tile * 64 + tid;
        if (PHASE == 1) {
            int n = m / 36, p = m - n * 36, oy = p / 6, ox = p - oy * 6;
            s_basix[tid] = (n * 64 + oy * 8 + ox) * 512;
        } else {
            int n = m >> 4, p = m & 15, oy = p >> 2, ox = p & 3;
            s_basix[tid] = (n * 36 + oy * 6 + ox) * 256;
        }
    }
    uint32_t mbf[2];
#pragma unroll
    for (int s = 0; s < 2; ++s) mbf[s] = smem_u32(&s_mb[s]);
    if (tid == 0) { MBINIT(mbf[0], 1); MBINIT(mbf[1], 1); }
    __syncthreads();

    const __half *Ap, *Bp;
    if (PHASE == 1) { Ap = g_x16;      Bp = g_w1b[head]; }
    else            { Ap = g_m1[head]; Bp = g_w2b[head]; }

    // A producer: 4x cp.async.cg per thread into stage c%3
    auto prefetchA = [&](int c) {
        const int kpos = c / CPK;
        const int coff = (c - kpos * CPK) * 64;
        const int ky = kpos / 3, kx = kpos - ky * 3;
        const int kadd = (PHASE == 1) ? ((ky * 8 + kx) * 512 + coff)
                                      : ((ky * 6 + kx) * 256 + coff);
        const uint32_t stg = sbase + (c % 3) * A_STAGE;
#pragma unroll
        for (int i = 0; i < 4; ++i) {                      // A: 64 rows x 128B
            int idx = tid + i * 128;
            int r = idx >> 3, seg = idx & 7;
            size_t e = (size_t)s_basix[r] + kadd + seg * 8;
            uint32_t off = (uint32_t)(r * A_PITCH + seg * 16);
            uint32_t sw = off ^ ((uint32_t)(r & 7) << 4);
            cpa16(stg + sw, Ap + e);
        }
        CP_COMMIT();
    };

    float acc[4][8][4];
#pragma unroll
    for (int mt = 0; mt < 4; ++mt)
#pragma unroll
        for (int nt = 0; nt < 8; ++nt)
#pragma unroll
            for (int q = 0; q < 4; ++q) acc[mt][nt][q] = 0.f;

    // prologue: A chunks 0,1 ; B chunks 0,1
    prefetchA(0);
    prefetchA(1);
    if (tid == 0) {
        MBEXPECT(mbf[0], B_BYTES);
        bulk_g2s(sbase + B_BASE,           Bp,                      B_BYTES, mbf[0]);
        MBEXPECT(mbf[1], B_BYTES);
        bulk_g2s(sbase + B_BASE + B_STAGE, Bp + (size_t)(256 * 72), B_BYTES, mbf[1]);
    }

    const uint32_t lrow = lane & 15;
    const uint32_t lhi  = (uint32_t)(lane >> 4) << 4;

    // per-warp invariant pieces of the ldmatrix addresses
    uint32_t aoffs[4], boffs[4];
#pragma unroll
    for (int mt = 0; mt < 4; ++mt) {
        uint32_t row = (uint32_t)(mt * 16) + lrow;
        aoffs[mt] = (row * A_PITCH + lhi) ^ ((row & 7) << 4);
    }
#pragma unroll
    for (int nt2 = 0; nt2 < 4; ++nt2) {
        uint32_t row = (uint32_t)(wn + nt2 * 16) + lrow;
        boffs[nt2] = row * B_PITCH + lhi;
    }

#pragma unroll 1
    for (int c = 0; c < CHUNKS; ++c) {
        MBWAIT(mbf[c & 1], (c >> 1) & 1);          // B of chunk c arrived
        if (c + 1 < CHUNKS) CP_WAIT1(); else CP_WAIT0();  // own A group c done
        __syncthreads();                           // publish A copies; chunk c-1 fully read
        if (c + 2 < CHUNKS) prefetchA(c + 2);      // stage (c+2)%3 free; overlap with compute

        const uint32_t stgA = sbase + (c % 3) * A_STAGE;
        const uint32_t stgB = sbase + B_BASE + (c & 1) * B_STAGE;

        uint32_t ah[2][4][4], bh[2][4][4];
        // preload ks=0 frags
#pragma unroll
        for (int mt = 0; mt < 4; ++mt) ldm4(ah[0][mt], stgA + aoffs[mt]);
#pragma unroll
        for (int nt2 = 0; nt2 < 4; ++nt2) ldm4(bh[0][nt2], stgB + boffs[nt2]);

#pragma unroll
        for (int ks = 0; ks < 4; ++ks) {
            const int cur = ks & 1, nxt = cur ^ 1;
            if (ks < 3) {
                const uint32_t kb = (uint32_t)(ks + 1) * 32;
#pragma unroll
                for (int mt = 0; mt < 4; ++mt) ldm4(ah[nxt][mt], stgA + (aoffs[mt] ^ kb));
#pragma unroll
                for (int nt2 = 0; nt2 < 4; ++nt2) ldm4(bh[nxt][nt2], stgB + boffs[nt2] + kb);
            }
#pragma unroll
            for (int mt = 0; mt < 4; ++mt)
#pragma unroll
                for (int nt = 0; nt < 8; ++nt)
                    mma16816(acc[mt][nt], ah[cur][mt],
                             bh[cur][nt >> 1][nt & 1], bh[cur][nt >> 1][(nt & 1) + 2]);
        }

        __syncthreads();                           // all warps done reading B stage (c&1)
        if (tid == 0 && c + 2 < CHUNKS) {
            MBEXPECT(mbf[c & 1], B_BYTES);
            bulk_g2s(stgB, Bp + (size_t)(c + 2) * (256 * 72), B_BYTES, mbf[c & 1]);
        }
    }

    // ---- epilogue: frags -> smem -> (bias, relu) -> global ----
    float* epi = (float*)dsm;
    __syncthreads();
#pragma unroll
    for (int mt = 0; mt < 4; ++mt)
#pragma unroll
        for (int nt = 0; nt < 8; ++nt) {
            int r0 = mt * 16 + (lane >> 2);
            int c0 = wn + nt * 8 + (lane & 3) * 2;
            *(float2*)&epi[r0 * EPI_PITCH + c0]       = make_float2(acc[mt][nt][0], acc[mt][nt][1]);
            *(float2*)&epi[(r0 + 8) * EPI_PITCH + c0] = make_float2(acc[mt][nt][2], acc[mt][nt][3]);
        }
    __syncthreads();

    if (PHASE == 1) {
        size_t mb_ = (size_t)tile * 64;
        const float b0 = bias[tid], b1 = bias[tid + 128];
#pragma unroll 1
        for (int i = 0; i < 64; ++i) {
            float v0 = fmaxf(epi[i * EPI_PITCH + tid] + b0, 0.f);
            float v1 = fmaxf(epi[i * EPI_PITCH + tid + 128] + b1, 0.f);
            g_m1[head][(mb_ + i) * 256 + tid]       = __float2half_rn(v0);
            g_m1[head][(mb_ + i) * 256 + tid + 128] = __float2half_rn(v1);
        }
    } else {
        float* outp = g_qkv[head] + (size_t)tile * 4 * 4096;
#pragma unroll 1
        for (int i = 0; i < 128; ++i) {
            int idx = tid + i * 128;
            int nl = idx >> 12, f = idx & 4095;
            int cout = f >> 4, p = f & 15;
            outp[idx] = fmaxf(epi[(nl * 16 + p) * EPI_PITCH + cout] + bias[cout], 0.f);
        }
    }
}

// ---------------- tiled block-diagonal attention ----------------------------------
// one block per 8 consecutive queries; union key segment is contiguous (sorted ids).
#define SMEM_ATT ((32768 + 16384 + 2048) * 4)

__global__ __launch_bounds__(256, 1)
void k_attn(const int* __restrict__ gid32, float* __restrict__ out) {
    extern __shared__ __align__(16) float asm_[];
    float* qsm  = asm_;                       // 8 x 4096
    float* srow = asm_ + 32768;               // 8 x 2048 (scores -> probs)
    int*   sgid = (int*)(asm_ + 32768 + 16384);

    __shared__ int s_jlo, s_jhi, s_rowg[8];

    const int qbase = blockIdx.x * 8;
    const int tid = threadIdx.x, warp = tid >> 5, lane = tid & 31;
    const int st = g_stride;

    if (tid == 0) {
        int g0 = gid32[qbase * st];
        int a = 0, b = NE;
        while (a < b) { int m = (a + b) >> 1; if (gid32[m * st] < g0) a = m + 1; else b = m; }
        s_jlo = a;
        int g7 = gid32[(qbase + 7) * st];
        a = 0; b = NE;
        while (a < b) { int m = (a + b) >> 1; if (gid32[m * st] <= g7) a = m + 1; else b = m; }
        s_jhi = a;
    }
    if (tid < 8) s_rowg[tid] = gid32[(qbase + tid) * st];
    __syncthreads();
    const int jlo = s_jlo, jhi = s_jhi, W = jhi - jlo;

    const float* qf = g_qkv[0];
    const float* kf = g_qkv[1];
    const float* vf = g_qkv[2];

    {
        const float4* qg = (const float4*)(qf + (size_t)qbase * 4096);
        float4* q4 = (float4*)qsm;
#pragma unroll
        for (int i = 0; i < 32; ++i) q4[tid + i * 256] = qg[tid + i * 256];
    }
    for (int t = tid; t < W; t += 256) sgid[t] = gid32[(jlo + t) * st];
    __syncthreads();

    // ---- scores: 4 keys x 8 queries register blocking, one group of 4 per warp ----
    const float4* q4 = (const float4*)qsm;
    for (int j0 = jlo + warp * 4; j0 < jhi; j0 += 32) {
        float acc[4][8];
#pragma unroll
        for (int jj = 0; jj < 4; ++jj)
#pragma unroll
            for (int r = 0; r < 8; ++r) acc[jj][r] = 0.f;

        const float4* kp[4];
#pragma unroll
        for (int jj = 0; jj < 4; ++jj) {
            int jc = j0 + jj; if (jc >= jhi) jc = jhi - 1;
            kp[jj] = (const float4*)(kf + (size_t)jc * 4096);
        }
#pragma unroll 2
        for (int t = lane; t < 1024; t += 32) {
            float4 kv[4];
#pragma unroll
            for (int jj = 0; jj < 4; ++jj) kv[jj] = kp[jj][t];
#pragma unroll
            for (int r = 0; r < 8; ++r) {
                float4 qv = q4[r * 1024 + t];
#pragma unroll
                for (int jj = 0; jj < 4; ++jj) {
                    acc[jj][r] = fmaf(kv[jj].x, qv.x, acc[jj][r]);
                    acc[jj][r] = fmaf(kv[jj].y, qv.y, acc[jj][r]);
                    acc[jj][r] = fmaf(kv[jj].z, qv.z, acc[jj][r]);
                    acc[jj][r] = fmaf(kv[jj].w, qv.w, acc[jj][r]);
                }
            }
        }
#pragma unroll
        for (int jj = 0; jj < 4; ++jj)
#pragma unroll
            for (int r = 0; r < 8; ++r) {
                float v = acc[jj][r];
#pragma unroll
                for (int o = 16; o; o >>= 1) v += __shfl_xor_sync(0xffffffffu, v, o);
                if (lane == 0 && j0 + jj < jhi)
                    srow[r * 2048 + (j0 + jj - jlo)] = v * SCALE;
            }
    }
    __syncthreads();

    // ---- masked softmax: warp w owns query row w ----
    if (warp < 8) {
        const int r = warp;
        const int gr = s_rowg[r];
        float* sr = srow + r * 2048;
        float m = -INFINITY;
        for (int t = lane; t < W; t += 32)
            if (sgid[t] == gr) m = fmaxf(m, sr[t]);
#pragma unroll
        for (int o = 16; o; o >>= 1) m = fmaxf(m, __shfl_xor_sync(0xffffffffu, m, o));
        float ssum = 0.f;
        for (int t = lane; t < W; t += 32) {
            float e = (sgid[t] == gr) ? __expf(sr[t] - m) : 0.f;
            sr[t] = e;
            ssum += e;
        }
#pragma unroll
        for (int o = 16; o; o >>= 1) ssum += __shfl_xor_sync(0xffffffffu, ssum, o);
        float inv = 1.f / ssum;
        for (int t = lane; t < W; t += 32) sr[t] *= inv;
    }
    __syncthreads();

    // ---- AV: out tile 8 x 4096, two feature halves (64 accum regs each) ----
#pragma unroll 1
    for (int hh = 0; hh < 2; ++hh) {
        float4 a0[8], a1[8];
#pragma unroll
        for (int r = 0; r < 8; ++r) {
            a0[r] = make_float4(0.f, 0.f, 0.f, 0.f);
            a1[r] = a0[r];
        }
        const int f4 = hh * 512 + tid * 2;
#pragma unroll 1
        for (int jt = 0; jt < W; ++jt) {
            const float4* vp = (const float4*)(vf + (size_t)(jlo + jt) * 4096) + f4;
            float4 v0 = vp[0], v1 = vp[1];
#pragma unroll
            for (int r = 0; r < 8; ++r) {
                float p = srow[r * 2048 + jt];
                a0[r].x = fmaf(p, v0.x, a0[r].x); a0[r].y = fmaf(p, v0.y, a0[r].y);
                a0[r].z = fmaf(p, v0.z, a0[r].z); a0[r].w = fmaf(p, v0.w, a0[r].w);
                a1[r].x = fmaf(p, v1.x, a1[r].x); a1[r].y = fmaf(p, v1.y, a1[r].y);
                a1[r].z = fmaf(p, v1.z, a1[r].z); a1[r].w = fmaf(p, v1.w, a1[r].w);
            }
        }
#pragma unroll
        for (int r = 0; r < 8; ++r) {
            float4* op = (float4*)(out + (size_t)(qbase + r) * 4096) + f4;
            op[0] = a0[r];
            op[1] = a1[r];
        }
    }
}

// ---------------- launch ----------------------------------------------------------
extern "C" void kernel_launch(void* const* d_in, const int* in_sizes, int n_in,
                              void* d_out, int out_size) {
    const float* x     = (const float*)d_in[0];
    const int*   gid32 = (const int*)d_in[1];

    const float* w1[3] = {(const float*)d_in[2], (const float*)d_in[6],  (const float*)d_in[10]};
    const float* b1[3] = {(const float*)d_in[3], (const float*)d_in[7],  (const float*)d_in[11]};
    const float* w2[3] = {(const float*)d_in[4], (const float*)d_in[8],  (const float*)d_in[12]};
    const float* b2[3] = {(const float*)d_in[5], (const float*)d_in[9],  (const float*)d_in[13]};

    cudaFuncSetAttribute(k_gemm<1>, cudaFuncAttributeMaxDynamicSharedMemorySize, SMEM_DYN);
    cudaFuncSetAttribute(k_gemm<2>, cudaFuncAttributeMaxDynamicSharedMemorySize, SMEM_DYN);
    cudaFuncSetAttribute(k_attn,    cudaFuncAttributeMaxDynamicSharedMemorySize, SMEM_ATT);

    // order chosen so the profiler's fixed launch-skip lands on k_gemm<1>
    k_prep_x<<<dim3(2048, 8), 256>>>(x);
    k_prep_w1<<<dim3(72, 3), 256>>>(w1[0], w1[1], w1[2]);
    k_prep_w2<<<dim3(36, 3), 256>>>(w2[0], w2[1], w2[2]);

    k_gemm<1><<<dim3(1152, 3), 128, SMEM_DYN>>>(b1[0], b1[1], b1[2]);
    k_gemm<2><<<dim3(512, 3), 128, SMEM_DYN>>>(b2[0], b2[1], b2[2]);

    k_detect<<<1, 256>>>(gid32);
    k_attn<<<256, 256, SMEM_ATT>>>(gid32, (float*)d_out);
}

// round 17
// speedup vs baseline: 1.0435x; 1.0435x over previous
#include <cuda_runtime.h>
#include <cuda_fp16.h>
#include <math.h>
#include <stdint.h>

#define NE 2048
#define SCALE 0.04419417382415922f   /* 1/sqrt(2*256) */

// ---------------- device scratch (static globals; no allocation) ----------------
__device__ __align__(16) __half g_x16[(size_t)NE * 64 * 512];   // x NHWC fp16
__device__ __align__(16) __half g_w1b[3][72 * 256 * 72];        // conv1 W chunk64-blocked pitch-144B
__device__ __align__(16) __half g_w2b[3][36 * 256 * 72];        // conv2 W chunk64-blocked
__device__ __align__(16) __half g_m1[3][(size_t)73728 * 256];   // conv1 out fp16
__device__ __align__(16) __half g_qkv16[3][(size_t)NE * 4096];  // conv2 out fp16 (q/k/v)
__device__ int   g_stride;

// ---------------- PTX helpers (compute_103 base ISA only) -------------------------
__device__ __forceinline__ uint32_t smem_u32(const void* p) {
    uint32_t a;
    asm("{ .reg .u64 t; cvta.to.shared.u64 t, %1; cvt.u32.u64 %0, t; }" : "=r"(a) : "l"(p));
    return a;
}
__device__ __forceinline__ void cpa16(uint32_t dst, const void* src) {
    asm volatile("cp.async.cg.shared.global [%0], [%1], 16;" :: "r"(dst), "l"(src) : "memory");
}
#define CP_COMMIT() asm volatile("cp.async.commit_group;" ::: "memory")
#define CP_WAIT1()  asm volatile("cp.async.wait_group 1;" ::: "memory")
#define CP_WAIT0()  asm volatile("cp.async.wait_group 0;" ::: "memory")

__device__ __forceinline__ void bulk_g2s(uint32_t dst, const void* src, uint32_t bytes,
                                         uint32_t mbar) {
    asm volatile("cp.async.bulk.shared::cluster.global.mbarrier::complete_tx::bytes "
                 "[%0], [%1], %2, [%3];"
                 :: "r"(dst), "l"(src), "r"(bytes), "r"(mbar) : "memory");
}
#define MBINIT(mb, c)    asm volatile("mbarrier.init.shared.b64 [%0], %1;" :: "r"(mb), "r"(c) : "memory")
#define MBEXPECT(mb, tx) asm volatile("mbarrier.arrive.expect_tx.shared.b64 _, [%0], %1;" :: "r"(mb), "r"(tx) : "memory")

#define MBWAIT(mb, ph) do {                                                              \
    uint32_t _m = (mb); uint32_t _p = (ph); uint32_t _d;                                 \
    asm volatile("{\n\t.reg .pred p;\n\t"                                                \
        "mbarrier.try_wait.parity.acquire.cta.shared::cta.b64 p, [%1], %2;\n\t"          \
        "selp.b32 %0, 1, 0, p;\n\t}" : "=r"(_d) : "r"(_m), "r"(_p) : "memory");          \
    if (!_d) {                                                                           \
        asm volatile("{\n\t.reg .pred P1;\n\t"                                           \
            "WL_%=:\n\t"                                                                 \
            "mbarrier.try_wait.parity.acquire.cta.shared::cta.b64 P1, [%0], %1, 0x989680;\n\t" \
            "@P1 bra.uni WD_%=;\n\t"                                                     \
            "bra.uni WL_%=;\n\t"                                                         \
            "WD_%=:\n\t}" :: "r"(_m), "r"(_p) : "memory");                               \
    }                                                                                    \
} while (0)

__device__ __forceinline__ void ldm4(uint32_t* r, uint32_t addr) {
    asm volatile("ldmatrix.sync.aligned.m8n8.x4.shared.b16 {%0,%1,%2,%3}, [%4];"
        : "=r"(r[0]), "=r"(r[1]), "=r"(r[2]), "=r"(r[3]) : "r"(addr));
}
__device__ __forceinline__ void mma16816(float* d, const uint32_t* a, uint32_t b0, uint32_t b1) {
    asm volatile("mma.sync.aligned.m16n8k16.row.col.f32.f16.f16.f32 "
        "{%0,%1,%2,%3}, {%4,%5,%6,%7}, {%8,%9}, {%0,%1,%2,%3};"
        : "+f"(d[0]), "+f"(d[1]), "+f"(d[2]), "+f"(d[3])
        : "r"(a[0]), "r"(a[1]), "r"(a[2]), "r"(a[3]), "r"(b0), "r"(b1));
}

// ---------------- graph-id dtype detection ---------------------------------------
__global__ void k_detect(const int* __restrict__ gid32) {
    __shared__ int bad;
    if (threadIdx.x == 0) bad = 0;
    __syncthreads();
    for (int i = threadIdx.x; i < NE - 1; i += blockDim.x)
        if (gid32[i] > gid32[i + 1]) bad = 1;
    __syncthreads();
    if (threadIdx.x == 0) g_stride = bad ? 2 : 1;
}

// ---------------- prep: x NCHW fp32 -> NHWC fp16 ----------------------------------
__global__ void k_prep_x(const float* __restrict__ x) {      // grid (2048, 8), 256 thr
    __shared__ float tile[64][65];
    const int n = blockIdx.x, cc = blockIdx.y;
#pragma unroll
    for (int i = 0; i < 16; ++i) {
        int t = threadIdx.x + i * 256;
        int ci = t >> 6, yx = t & 63;
        tile[ci][yx] = x[(size_t)n * 32768 + (cc * 64 + ci) * 64 + yx];
    }
    __syncthreads();
#pragma unroll
    for (int i = 0; i < 16; ++i) {
        int t = threadIdx.x + i * 256;
        int yx = t >> 6, ci = t & 63;
        size_t o = ((size_t)n * 64 + yx) * 512 + cc * 64 + ci;
        g_x16[o] = __float2half_rn(tile[ci][yx]);
    }
}

// ---------------- prep: weights -> chunk64-blocked [c][cout][72] (pitch 144B) -----
__global__ void k_prep_w1(const float* __restrict__ wq, const float* __restrict__ wk,
                          const float* __restrict__ wv) {    // grid (72, 3), 256 thr
    const int c = blockIdx.x, h = blockIdx.y;
    const float* w = (h == 0) ? wq : (h == 1) ? wk : wv;
    const int kpos = c >> 3, coff = (c & 7) * 64;
    const int cout = threadIdx.x;
    __half* dst = g_w1b[h] + ((size_t)c * 256 + cout) * 72;
#pragma unroll
    for (int j = 0; j < 64; ++j)
        dst[j] = __float2half_rn(w[cout * 4608 + (coff + j) * 9 + kpos]);
#pragma unroll
    for (int j = 64; j < 72; ++j) dst[j] = __float2half_rn(0.f);
}

__global__ void k_prep_w2(const float* __restrict__ wq, const float* __restrict__ wk,
                          const float* __restrict__ wv) {    // grid (36, 3), 256 thr
    const int c = blockIdx.x, h = blockIdx.y;
    const float* w = (h == 0) ? wq : (h == 1) ? wk : wv;
    const int kpos = c >> 2, coff = (c & 3) * 64;
    const int cout = threadIdx.x;
    __half* dst = g_w2b[h] + ((size_t)c * 256 + cout) * 72;
#pragma unroll
    for (int j = 0; j < 64; ++j)
        dst[j] = __float2half_rn(w[cout * 2304 + (coff + j) * 9 + kpos]);
#pragma unroll
    for (int j = 64; j < 72; ++j) dst[j] = __float2half_rn(0.f);
}

// ---------------- HMMA GEMM: conv1 (PHASE 1) / conv2 (PHASE 2) --------------------
// CTA: M=64 x N=256, 128 threads (4 warps of 64x64), 2 CTAs/SM. K chunks of 64.
// A: 3 stages x 8KB (pitch 128, XOR swizzle), cp.async.cg, issued after top barrier.
// B: 2 stages x 36KB (pitch 144), ONE bulk each, issued after bottom barrier.
#define A_STAGE     8192
#define A_PITCH     128
#define B_BASE      24576
#define B_STAGE     36864
#define B_PITCH     144
#define B_BYTES     36864u
#define SMEM_DYN    98304
#define EPI_PITCH   260

template <int PHASE>
__global__ void __launch_bounds__(128, 2)
k_gemm(const float* __restrict__ bq, const float* __restrict__ bk,
       const float* __restrict__ bv) {
    extern __shared__ __align__(1024) char dsm[];
    const uint32_t sbase = smem_u32(dsm);

    const int tile = blockIdx.x, head = blockIdx.y;
    const int tid  = threadIdx.x, wid = tid >> 5, lane = tid & 31;
    const int wn   = wid * 64;               // warp n offset (wm = 0 for all)
    const float* bias = (head == 0) ? bq : (head == 1) ? bk : bv;

    __shared__ int s_basix[64];
    __shared__ __align__(8) unsigned long long s_mb[2];   // B full barriers

    constexpr int CHUNKS = (PHASE == 1) ? 72 : 36;
    constexpr int CPK    = (PHASE == 1) ? 8 : 4;

    if (tid < 64) {
        int m = tile * 64 + tid;
        if (PHASE == 1) {
            int n = m / 36, p = m - n * 36, oy = p / 6, ox = p - oy * 6;
            s_basix[tid] = (n * 64 + oy * 8 + ox) * 512;
        } else {
            int n = m >> 4, p = m & 15, oy = p >> 2, ox = p & 3;
            s_basix[tid] = (n * 36 + oy * 6 + ox) * 256;
        }
    }
    uint32_t mbf[2];
#pragma unroll
    for (int s = 0; s < 2; ++s) mbf[s] = smem_u32(&s_mb[s]);
    if (tid == 0) { MBINIT(mbf[0], 1); MBINIT(mbf[1], 1); }
    __syncthreads();

    const __half *Ap, *Bp;
    if (PHASE == 1) { Ap = g_x16;      Bp = g_w1b[head]; }
    else            { Ap = g_m1[head]; Bp = g_w2b[head]; }

    // A producer: 4x cp.async.cg per thread into stage c%3
    auto prefetchA = [&](int c) {
        const int kpos = c / CPK;
        const int coff = (c - kpos * CPK) * 64;
        const int ky = kpos / 3, kx = kpos - ky * 3;
        const int kadd = (PHASE == 1) ? ((ky * 8 + kx) * 512 + coff)
                                      : ((ky * 6 + kx) * 256 + coff);
        const uint32_t stg = sbase + (c % 3) * A_STAGE;
#pragma unroll
        for (int i = 0; i < 4; ++i) {                      // A: 64 rows x 128B
            int idx = tid + i * 128;
            int r = idx >> 3, seg = idx & 7;
            size_t e = (size_t)s_basix[r] + kadd + seg * 8;
            uint32_t off = (uint32_t)(r * A_PITCH + seg * 16);
            uint32_t sw = off ^ ((uint32_t)(r & 7) << 4);
            cpa16(stg + sw, Ap + e);
        }
        CP_COMMIT();
    };

    float acc[4][8][4];
#pragma unroll
    for (int mt = 0; mt < 4; ++mt)
#pragma unroll
        for (int nt = 0; nt < 8; ++nt)
#pragma unroll
            for (int q = 0; q < 4; ++q) acc[mt][nt][q] = 0.f;

    // prologue: A chunks 0,1 ; B chunks 0,1
    prefetchA(0);
    prefetchA(1);
    if (tid == 0) {
        MBEXPECT(mbf[0], B_BYTES);
        bulk_g2s(sbase + B_BASE,           Bp,                      B_BYTES, mbf[0]);
        MBEXPECT(mbf[1], B_BYTES);
        bulk_g2s(sbase + B_BASE + B_STAGE, Bp + (size_t)(256 * 72), B_BYTES, mbf[1]);
    }

    const uint32_t lrow = lane & 15;
    const uint32_t lhi  = (uint32_t)(lane >> 4) << 4;

#pragma unroll 1
    for (int c = 0; c < CHUNKS; ++c) {
        MBWAIT(mbf[c & 1], (c >> 1) & 1);          // B of chunk c arrived
        if (c + 1 < CHUNKS) CP_WAIT1(); else CP_WAIT0();  // own A group c done
        __syncthreads();                           // publish A copies; chunk c-1 fully read
        if (c + 2 < CHUNKS) prefetchA(c + 2);      // stage (c+2)%3 free; overlap with compute

        const uint32_t stgA = sbase + (c % 3) * A_STAGE;
        const uint32_t stgB = sbase + B_BASE + (c & 1) * B_STAGE;

#pragma unroll
        for (int ks = 0; ks < 4; ++ks) {
            uint32_t ah[4][4], bh[4][4];
#pragma unroll
            for (int mt = 0; mt < 4; ++mt) {
                uint32_t row = (uint32_t)(mt * 16) + lrow;
                uint32_t off = row * A_PITCH + (uint32_t)ks * 32 + lhi;
                ldm4(ah[mt], stgA + (off ^ ((row & 7) << 4)));
            }
#pragma unroll
            for (int nt2 = 0; nt2 < 4; ++nt2) {
                uint32_t row = (uint32_t)(wn + nt2 * 16) + lrow;
                ldm4(bh[nt2], stgB + row * B_PITCH + (uint32_t)ks * 32 + lhi);
            }
#pragma unroll
            for (int mt = 0; mt < 4; ++mt)
#pragma unroll
                for (int nt = 0; nt < 8; ++nt)
                    mma16816(acc[mt][nt], ah[mt], bh[nt >> 1][nt & 1], bh[nt >> 1][(nt & 1) + 2]);
        }

        __syncthreads();                           // all warps done reading B stage (c&1)
        if (tid == 0 && c + 2 < CHUNKS) {
            MBEXPECT(mbf[c & 1], B_BYTES);
            bulk_g2s(stgB, Bp + (size_t)(c + 2) * (256 * 72), B_BYTES, mbf[c & 1]);
        }
    }

    // ---- epilogue: frags -> smem -> (bias, relu) -> global ----
    float* epi = (float*)dsm;
    __syncthreads();
#pragma unroll
    for (int mt = 0; mt < 4; ++mt)
#pragma unroll
        for (int nt = 0; nt < 8; ++nt) {
            int r0 = mt * 16 + (lane >> 2);
            int c0 = wn + nt * 8 + (lane & 3) * 2;
            *(float2*)&epi[r0 * EPI_PITCH + c0]       = make_float2(acc[mt][nt][0], acc[mt][nt][1]);
            *(float2*)&epi[(r0 + 8) * EPI_PITCH + c0] = make_float2(acc[mt][nt][2], acc[mt][nt][3]);
        }
    __syncthreads();

    if (PHASE == 1) {
        size_t mb_ = (size_t)tile * 64;
        const float b0 = bias[tid], b1 = bias[tid + 128];
#pragma unroll 1
        for (int i = 0; i < 64; ++i) {
            float v0 = fmaxf(epi[i * EPI_PITCH + tid] + b0, 0.f);
            float v1 = fmaxf(epi[i * EPI_PITCH + tid + 128] + b1, 0.f);
            g_m1[head][(mb_ + i) * 256 + tid]       = __float2half_rn(v0);
            g_m1[head][(mb_ + i) * 256 + tid + 128] = __float2half_rn(v1);
        }
    } else {
        __half* outp = g_qkv16[head] + (size_t)tile * 4 * 4096;
#pragma unroll 1
        for (int i = 0; i < 128; ++i) {
            int idx = tid + i * 128;
            int nl = idx >> 12, f = idx & 4095;
            int cout = f >> 4, p = f & 15;
            outp[idx] = __float2half_rn(
                fmaxf(epi[(nl * 16 + p) * EPI_PITCH + cout] + bias[cout], 0.f));
        }
    }
}

// ---------------- tiled block-diagonal attention (fp16 q/k/v) ---------------------
// one block per 8 consecutive queries; union key segment is contiguous (sorted ids).
// smem: q fp16 8x4096 (64KB) | srow fp32 8x2048 (64KB) | sgid 2048 ints (8KB)
#define SMEM_ATT (65536 + 65536 + 8192)

__global__ __launch_bounds__(256, 1)
void k_attn(const int* __restrict__ gid32, float* __restrict__ out) {
    extern __shared__ __align__(16) char asm_[];
    __half* qsm  = (__half*)asm_;
    float*  srow = (float*)(asm_ + 65536);
    int*    sgid = (int*)(asm_ + 131072);

    __shared__ int s_jlo, s_jhi, s_rowg[8];

    const int qbase = blockIdx.x * 8;
    const int tid = threadIdx.x, warp = tid >> 5, lane = tid & 31;
    const int st = g_stride;

    if (tid == 0) {
        int g0 = gid32[qbase * st];
        int a = 0, b = NE;
        while (a < b) { int m = (a + b) >> 1; if (gid32[m * st] < g0) a = m + 1; else b = m; }
        s_jlo = a;
        int g7 = gid32[(qbase + 7) * st];
        a = 0; b = NE;
        while (a < b) { int m = (a + b) >> 1; if (gid32[m * st] <= g7) a = m + 1; else b = m; }
        s_jhi = a;
    }
    if (tid < 8) s_rowg[tid] = gid32[(qbase + tid) * st];
    __syncthreads();
    const int jlo = s_jlo, jhi = s_jhi, W = jhi - jlo;

    const __half* qf = g_qkv16[0];
    const __half* kf = g_qkv16[1];
    const __half* vf = g_qkv16[2];

    // load 8 q rows: 8 x 4096 halves = 4096 uint4
    {
        const uint4* qg = (const uint4*)(qf + (size_t)qbase * 4096);
        uint4* q4 = (uint4*)qsm;
#pragma unroll
        for (int i = 0; i < 16; ++i) q4[tid + i * 256] = qg[tid + i * 256];
    }
    for (int t = tid; t < W; t += 256) sgid[t] = gid32[(jlo + t) * st];
    __syncthreads();

    // ---- scores: 4 keys x 8 queries register blocking, one group of 4 per warp ----
    const uint4* q4 = (const uint4*)qsm;
    for (int j0 = jlo + warp * 4; j0 < jhi; j0 += 32) {
        float acc[4][8];
#pragma unroll
        for (int jj = 0; jj < 4; ++jj)
#pragma unroll
            for (int r = 0; r < 8; ++r) acc[jj][r] = 0.f;

        const uint4* kp[4];
#pragma unroll
        for (int jj = 0; jj < 4; ++jj) {
            int jc = j0 + jj; if (jc >= jhi) jc = jhi - 1;
            kp[jj] = (const uint4*)(kf + (size_t)jc * 4096);
        }
#pragma unroll 2
        for (int t = lane; t < 512; t += 32) {     // 512 uint4 (8 halves) per row
            float2 kfv[4][4];
#pragma unroll
            for (int jj = 0; jj < 4; ++jj) {
                uint4 kv = kp[jj][t];
                kfv[jj][0] = __half22float2(*(const __half2*)&kv.x);
                kfv[jj][1] = __half22float2(*(const __half2*)&kv.y);
                kfv[jj][2] = __half22float2(*(const __half2*)&kv.z);
                kfv[jj][3] = __half22float2(*(const __half2*)&kv.w);
            }
#pragma unroll
            for (int r = 0; r < 8; ++r) {
                uint4 qv = q4[r * 512 + t];
                float2 qf0 = __half22float2(*(const __half2*)&qv.x);
                float2 qf1 = __half22float2(*(const __half2*)&qv.y);
                float2 qf2 = __half22float2(*(const __half2*)&qv.z);
                float2 qf3 = __half22float2(*(const __half2*)&qv.w);
#pragma unroll
                for (int jj = 0; jj < 4; ++jj) {
                    float s = acc[jj][r];
                    s = fmaf(qf0.x, kfv[jj][0].x, s); s = fmaf(qf0.y, kfv[jj][0].y, s);
                    s = fmaf(qf1.x, kfv[jj][1].x, s); s = fmaf(qf1.y, kfv[jj][1].y, s);
                    s = fmaf(qf2.x, kfv[jj][2].x, s); s = fmaf(qf2.y, kfv[jj][2].y, s);
                    s = fmaf(qf3.x, kfv[jj][3].x, s); s = fmaf(qf3.y, kfv[jj][3].y, s);
                    acc[jj][r] = s;
                }
            }
        }
#pragma unroll
        for (int jj = 0; jj < 4; ++jj)
#pragma unroll
            for (int r = 0; r < 8; ++r) {
                float v = acc[jj][r];
#pragma unroll
                for (int o = 16; o; o >>= 1) v += __shfl_xor_sync(0xffffffffu, v, o);
                if (lane == 0 && j0 + jj < jhi)
                    srow[r * 2048 + (j0 + jj - jlo)] = v * SCALE;
            }
    }
    __syncthreads();

    // ---- masked softmax: warp w owns query row w ----
    if (warp < 8) {
        const int r = warp;
        const int gr = s_rowg[r];
        float* sr = srow + r * 2048;
        float m = -INFINITY;
        for (int t = lane; t < W; t += 32)
            if (sgid[t] == gr) m = fmaxf(m, sr[t]);
#pragma unroll
        for (int o = 16; o; o >>= 1) m = fmaxf(m, __shfl_xor_sync(0xffffffffu, m, o));
        float ssum = 0.f;
        for (int t = lane; t < W; t += 32) {
            float e = (sgid[t] == gr) ? __expf(sr[t] - m) : 0.f;
            sr[t] = e;
            ssum += e;
        }
#pragma unroll
        for (int o = 16; o; o >>= 1) ssum += __shfl_xor_sync(0xffffffffu, ssum, o);
        float inv = 1.f / ssum;
        for (int t = lane; t < W; t += 32) sr[t] *= inv;
    }
    __syncthreads();

    // ---- AV: out tile 8 x 4096, two feature halves; each thread owns 8 feats/half
#pragma unroll 1
    for (int hh = 0; hh < 2; ++hh) {
        float acc[8][8];
#pragma unroll
        for (int r = 0; r < 8; ++r)
#pragma unroll
            for (int q = 0; q < 8; ++q) acc[r][q] = 0.f;

        const int fu = hh * 256 + tid;             // uint4 index within row (512/row)
#pragma unroll 1
        for (int jt = 0; jt < W; ++jt) {
            uint4 vv = ((const uint4*)(vf + (size_t)(jlo + jt) * 4096))[fu];
            float2 v0 = __half22float2(*(const __half2*)&vv.x);
            float2 v1 = __half22float2(*(const __half2*)&vv.y);
            float2 v2 = __half22float2(*(const __half2*)&vv.z);
            float2 v3 = __half22float2(*(const __half2*)&vv.w);
#pragma unroll
            for (int r = 0; r < 8; ++r) {
                float p = srow[r * 2048 + jt];
                acc[r][0] = fmaf(p, v0.x, acc[r][0]); acc[r][1] = fmaf(p, v0.y, acc[r][1]);
                acc[r][2] = fmaf(p, v1.x, acc[r][2]); acc[r][3] = fmaf(p, v1.y, acc[r][3]);
                acc[r][4] = fmaf(p, v2.x, acc[r][4]); acc[r][5] = fmaf(p, v2.y, acc[r][5]);
                acc[r][6] = fmaf(p, v3.x, acc[r][6]); acc[r][7] = fmaf(p, v3.y, acc[r][7]);
            }
        }
#pragma unroll
        for (int r = 0; r < 8; ++r) {
            float4* op = (float4*)(out + (size_t)(qbase + r) * 4096 + fu * 8);
            op[0] = make_float4(acc[r][0], acc[r][1], acc[r][2], acc[r][3]);
            op[1] = make_float4(acc[r][4], acc[r][5], acc[r][6], acc[r][7]);
        }
    }
}

// ---------------- launch ----------------------------------------------------------
extern "C" void kernel_launch(void* const* d_in, const int* in_sizes, int n_in,
                              void* d_out, int out_size) {
    const float* x     = (const float*)d_in[0];
    const int*   gid32 = (const int*)d_in[1];

    const float* w1[3] = {(const float*)d_in[2], (const float*)d_in[6],  (const float*)d_in[10]};
    const float* b1[3] = {(const float*)d_in[3], (const float*)d_in[7],  (const float*)d_in[11]};
    const float* w2[3] = {(const float*)d_in[4], (const float*)d_in[8],  (const float*)d_in[12]};
    const float* b2[3] = {(const float*)d_in[5], (const float*)d_in[9],  (const float*)d_in[13]};

    cudaFuncSetAttribute(k_gemm<1>, cudaFuncAttributeMaxDynamicSharedMemorySize, SMEM_DYN);
    cudaFuncSetAttribute(k_gemm<2>, cudaFuncAttributeMaxDynamicSharedMemorySize, SMEM_DYN);
    cudaFuncSetAttribute(k_attn,    cudaFuncAttributeMaxDynamicSharedMemorySize, SMEM_ATT);

    // order chosen so the profiler's fixed launch-skip lands on k_gemm<1>
    k_prep_x<<<dim3(2048, 8), 256>>>(x);
    k_prep_w1<<<dim3(72, 3), 256>>>(w1[0], w1[1], w1[2]);
    k_prep_w2<<<dim3(36, 3), 256>>>(w2[0], w2[1], w2[2]);

    k_gemm<1><<<dim3(1152, 3), 128, SMEM_DYN>>>(b1[0], b1[1], b1[2]);
    k_gemm<2><<<dim3(512, 3), 128, SMEM_DYN>>>(b2[0], b2[1], b2[2]);

    k_detect<<<1, 256>>>(gid32);
    k_attn<<<256, 256, SMEM_ATT>>>(gid32, (float*)d_out);
}